// round 15
// baseline (speedup 1.0000x reference)
#include <cuda_runtime.h>
#include <math.h>
#include <stdint.h>

#define N_NODES 50000
#define E_EDGES 600000
#define IN_DIM_ 512
#define HID_ 256
#define OUT_DIM_ 64

// ---------------- scratch (static device globals; no allocations) ----------
__device__ float g_hp1[(size_t)N_NODES * HID_];
__device__ float g_h1acc[(size_t)N_NODES * HID_];   // prop1 result; reused for prop2
__device__ float g_hp3[(size_t)N_NODES * HID_];
__device__ float g_as[N_NODES];
__device__ float g_ad[N_NODES];

// CSR by destination
__device__ int g_deg[N_NODES];
__device__ int g_start[N_NODES];
__device__ int g_cursor[N_NODES];
__device__ int g_csr_src[E_EDGES];
__device__ float g_csr_w[E_EDGES];

// prepped weights (all tf32, B[n][k] layout)
__device__ uint32_t g_b1t[256 * 512];               // W1^T  (N=256,K=512)
__device__ uint32_t g_b4t[512 * 256];               // W1    (N=512,K=256)
__device__ uint32_t g_b2t[64 * 256];                // W2^T  (N=64, K=256)
__device__ uint32_t g_b3t[256 * 64];                // W2    (N=256,K=64)

// ---------------- helpers -----------------------------------------------------
__device__ __forceinline__ float elu_f(float x) {
    return x > 0.f ? x : (expf(x) - 1.f);
}
__device__ __forceinline__ uint32_t f2tf32(float x) {
    uint32_t u;
    asm("cvt.rna.tf32.f32 %0, %1;" : "=r"(u) : "f"(x));
    return u;
}
__device__ __forceinline__ void mma_tf32(float* d, const uint32_t* a, const uint32_t* b) {
    asm volatile(
        "mma.sync.aligned.m16n8k8.row.col.f32.tf32.tf32.f32 "
        "{%0,%1,%2,%3}, {%4,%5,%6,%7}, {%8,%9}, {%0,%1,%2,%3};"
        : "+f"(d[0]), "+f"(d[1]), "+f"(d[2]), "+f"(d[3])
        : "r"(a[0]), "r"(a[1]), "r"(a[2]), "r"(a[3]), "r"(b[0]), "r"(b[1]));
}

// ---------------- CSR build ----------------------------------------------------
__global__ void zero_deg(int* deg) {
    int i = blockIdx.x * blockDim.x + threadIdx.x;
    if (i < N_NODES) deg[i] = 0;
}

__global__ void count_deg(const int* __restrict__ dst, int* __restrict__ deg) {
    int e = blockIdx.x * blockDim.x + threadIdx.x;
    if (e < E_EDGES) atomicAdd(&deg[dst[e]], 1);
}

__global__ void scan_deg(const int* __restrict__ deg, int* __restrict__ start,
                         int* __restrict__ cursor) {
    __shared__ int warp_sums[32];
    __shared__ int s_carry;
    if (threadIdx.x == 0) s_carry = 0;
    __syncthreads();
    const int tid = threadIdx.x;
    const int lane = tid & 31;
    const int wid = tid >> 5;
    for (int base = 0; base < N_NODES; base += 1024) {
        int i = base + tid;
        int v = (i < N_NODES) ? deg[i] : 0;
        int incl = v;
#pragma unroll
        for (int o = 1; o < 32; o <<= 1) {
            int t = __shfl_up_sync(0xffffffffu, incl, o);
            if (lane >= o) incl += t;
        }
        if (lane == 31) warp_sums[wid] = incl;
        __syncthreads();
        if (wid == 0) {
            int ws = warp_sums[lane];
            int wincl = ws;
#pragma unroll
            for (int o = 1; o < 32; o <<= 1) {
                int t = __shfl_up_sync(0xffffffffu, wincl, o);
                if (lane >= o) wincl += t;
            }
            warp_sums[lane] = wincl - ws;
        }
        __syncthreads();
        int excl = incl - v + warp_sums[wid] + s_carry;
        if (i < N_NODES) { start[i] = excl; cursor[i] = excl; }
        __syncthreads();
        if (tid == 1023) s_carry = excl + v;
        __syncthreads();
    }
}

__global__ void fill_csr(const int* __restrict__ src, const int* __restrict__ dst,
                         int* __restrict__ cursor, int* __restrict__ csr_src) {
    int e = blockIdx.x * blockDim.x + threadIdx.x;
    if (e >= E_EDGES) return;
    int pos = atomicAdd(&cursor[dst[e]], 1);
    csr_src[pos] = src[e];
}

// ---------------- fused softmax + propagate-1 (warp per dst) --------------------
__global__ void __launch_bounds__(256)
softmax_prop(const int* __restrict__ start, const int* __restrict__ deg,
             const int* __restrict__ csr_src,
             const float* __restrict__ a_s, const float* __restrict__ a_d,
             float* __restrict__ csr_w,
             const float* __restrict__ H, float* __restrict__ out) {
    int d = (blockIdx.x * blockDim.x + threadIdx.x) >> 5;
    int lane = threadIdx.x & 31;
    if (d >= N_NODES) return;
    int s0 = start[d], n = deg[d];

    float4 acc0 = make_float4(0.f, 0.f, 0.f, 0.f);
    float4 acc1 = make_float4(0.f, 0.f, 0.f, 0.f);

    if (n > 0 && n <= 64) {
        float ad = a_d[d];
        int se0 = 0, se1 = 0;
        float l0 = -INFINITY, l1 = -INFINITY;
        if (lane < n) {
            se0 = csr_src[s0 + lane];
            float x = a_s[se0] + ad;
            l0 = x > 0.f ? x : 0.2f * x;
        }
        if (lane + 32 < n) {
            se1 = csr_src[s0 + lane + 32];
            float x = a_s[se1] + ad;
            l1 = x > 0.f ? x : 0.2f * x;
        }
        float mx = fmaxf(l0, l1);
#pragma unroll
        for (int o = 16; o; o >>= 1) mx = fmaxf(mx, __shfl_xor_sync(0xffffffffu, mx, o));
        float w0 = (lane < n) ? expf(l0 - mx) : 0.f;
        float w1 = (lane + 32 < n) ? expf(l1 - mx) : 0.f;
        float sum = w0 + w1;
#pragma unroll
        for (int o = 16; o; o >>= 1) sum += __shfl_xor_sync(0xffffffffu, sum, o);
        float inv = 1.f / (sum + 1e-16f);
        w0 *= inv; w1 *= inv;
        if (lane < n) csr_w[s0 + lane] = w0;
        if (lane + 32 < n) csr_w[s0 + lane + 32] = w1;

        for (int i = 0; i < n; i++) {
            int si; float wi;
            if (i < 32) {
                si = __shfl_sync(0xffffffffu, se0, i);
                wi = __shfl_sync(0xffffffffu, w0, i);
            } else {
                si = __shfl_sync(0xffffffffu, se1, i - 32);
                wi = __shfl_sync(0xffffffffu, w1, i - 32);
            }
            const float4* r = (const float4*)(H + (size_t)si * HID_);
            float4 v0 = r[lane], v1 = r[lane + 32];
            acc0.x = fmaf(v0.x, wi, acc0.x); acc0.y = fmaf(v0.y, wi, acc0.y);
            acc0.z = fmaf(v0.z, wi, acc0.z); acc0.w = fmaf(v0.w, wi, acc0.w);
            acc1.x = fmaf(v1.x, wi, acc1.x); acc1.y = fmaf(v1.y, wi, acc1.y);
            acc1.z = fmaf(v1.z, wi, acc1.z); acc1.w = fmaf(v1.w, wi, acc1.w);
        }
    } else if (n > 64) {
        float ad = a_d[d];
        float mx = -INFINITY;
        for (int i = lane; i < n; i += 32) {
            float x = a_s[csr_src[s0 + i]] + ad;
            x = x > 0.f ? x : 0.2f * x;
            csr_w[s0 + i] = x;
            mx = fmaxf(mx, x);
        }
#pragma unroll
        for (int o = 16; o; o >>= 1) mx = fmaxf(mx, __shfl_xor_sync(0xffffffffu, mx, o));
        float sum = 0.f;
        for (int i = lane; i < n; i += 32) {
            float ex = expf(csr_w[s0 + i] - mx);
            csr_w[s0 + i] = ex;
            sum += ex;
        }
#pragma unroll
        for (int o = 16; o; o >>= 1) sum += __shfl_xor_sync(0xffffffffu, sum, o);
        float inv = 1.f / (sum + 1e-16f);
        for (int i = lane; i < n; i += 32) csr_w[s0 + i] *= inv;
        __threadfence_block();
        __syncwarp();
        for (int i = 0; i < n; i++) {
            int si = csr_src[s0 + i];
            float wi = csr_w[s0 + i];
            const float4* r = (const float4*)(H + (size_t)si * HID_);
            float4 v0 = r[lane], v1 = r[lane + 32];
            acc0.x = fmaf(v0.x, wi, acc0.x); acc0.y = fmaf(v0.y, wi, acc0.y);
            acc0.z = fmaf(v0.z, wi, acc0.z); acc0.w = fmaf(v0.w, wi, acc0.w);
            acc1.x = fmaf(v1.x, wi, acc1.x); acc1.y = fmaf(v1.y, wi, acc1.y);
            acc1.z = fmaf(v1.z, wi, acc1.z); acc1.w = fmaf(v1.w, wi, acc1.w);
        }
    }
    float4* orow = (float4*)(out + (size_t)d * HID_);
    orow[lane] = acc0;
    orow[lane + 32] = acc1;
}

// ---------------- propagate-2 (reads stored csr_w) --------------------------------
__global__ void __launch_bounds__(256)
propagate_csr(const int* __restrict__ start, const int* __restrict__ deg,
              const int* __restrict__ csr_src, const float* __restrict__ csr_w,
              const float* __restrict__ H, float* __restrict__ out) {
    int d = (blockIdx.x * blockDim.x + threadIdx.x) >> 5;
    int lane = threadIdx.x & 31;
    if (d >= N_NODES) return;
    int s0 = start[d], n = deg[d];
    float4 acc0 = make_float4(0.f, 0.f, 0.f, 0.f);
    float4 acc1 = make_float4(0.f, 0.f, 0.f, 0.f);
    int i = 0;
    for (; i + 2 <= n; i += 2) {
        int sA = csr_src[s0 + i], sB = csr_src[s0 + i + 1];
        float wA = csr_w[s0 + i], wB = csr_w[s0 + i + 1];
        const float4* rA = (const float4*)(H + (size_t)sA * HID_);
        const float4* rB = (const float4*)(H + (size_t)sB * HID_);
        float4 a0 = rA[lane], a1 = rA[lane + 32];
        float4 b0 = rB[lane], b1 = rB[lane + 32];
        acc0.x = fmaf(a0.x, wA, acc0.x); acc0.y = fmaf(a0.y, wA, acc0.y);
        acc0.z = fmaf(a0.z, wA, acc0.z); acc0.w = fmaf(a0.w, wA, acc0.w);
        acc1.x = fmaf(a1.x, wA, acc1.x); acc1.y = fmaf(a1.y, wA, acc1.y);
        acc1.z = fmaf(a1.z, wA, acc1.z); acc1.w = fmaf(a1.w, wA, acc1.w);
        acc0.x = fmaf(b0.x, wB, acc0.x); acc0.y = fmaf(b0.y, wB, acc0.y);
        acc0.z = fmaf(b0.z, wB, acc0.z); acc0.w = fmaf(b0.w, wB, acc0.w);
        acc1.x = fmaf(b1.x, wB, acc1.x); acc1.y = fmaf(b1.y, wB, acc1.y);
        acc1.z = fmaf(b1.z, wB, acc1.z); acc1.w = fmaf(b1.w, wB, acc1.w);
    }
    if (i < n) {
        int s = csr_src[s0 + i];
        float w = csr_w[s0 + i];
        const float4* r = (const float4*)(H + (size_t)s * HID_);
        float4 a0 = r[lane], a1 = r[lane + 32];
        acc0.x = fmaf(a0.x, w, acc0.x); acc0.y = fmaf(a0.y, w, acc0.y);
        acc0.z = fmaf(a0.z, w, acc0.z); acc0.w = fmaf(a0.w, w, acc0.w);
        acc1.x = fmaf(a1.x, w, acc1.x); acc1.y = fmaf(a1.y, w, acc1.y);
        acc1.z = fmaf(a1.z, w, acc1.z); acc1.w = fmaf(a1.w, w, acc1.w);
    }
    float4* orow = (float4*)(out + (size_t)d * HID_);
    orow[lane] = acc0;
    orow[lane + 32] = acc1;
}

// ---------------- weight prep (all tf32, + zero a_s/a_d) -----------------------------
__global__ void prep_weights(const float* __restrict__ W1, const float* __restrict__ W2,
                             uint32_t* b1t, uint32_t* b4t,
                             uint32_t* b2t, uint32_t* b3t,
                             float* a_s, float* a_d) {
    int i = blockIdx.x * blockDim.x + threadIdx.x;
    if (i < N_NODES) { a_s[i] = 0.f; a_d[i] = 0.f; }
    if (i < 512 * 256) {
        int k = i >> 8, n = i & 255;
        uint32_t t = f2tf32(W1[i]);
        b4t[i] = t;               // W1 direct  [512][256]
        b1t[n * 512 + k] = t;     // W1^T       [256][512]
    }
    if (i < 256 * 64) {
        int k = i >> 6, n = i & 63;
        uint32_t t = f2tf32(W2[i]);
        b3t[i] = t;               // W2 direct  [256][64]
        b2t[n * 256 + k] = t;     // W2^T       [64][256]
    }
}

// ---------------- unified tf32 GEMM (straight layout, conflict-free) -----------------
// C[M,N] = op(A)[M,K] @ Bt, Bt tf32 [N][K] rows. BM=128, BN=128, BK=32.
template <bool ELUA, bool ATT>
__global__ void __launch_bounds__(512)
tf32_gemm(const float* __restrict__ A, const uint32_t* __restrict__ Bt,
          float* __restrict__ C, int M, int N, int K,
          const float* __restrict__ attS, const float* __restrict__ attD,
          float* __restrict__ a_s, float* __restrict__ a_d) {
    constexpr int SPF = 36;
    constexpr int TSZ = 128 * SPF;

    extern __shared__ uint32_t smu[];

    const int tid = threadIdx.x;
    const int wid = tid >> 5;
    const int lane = tid & 31;
    const int wm = wid >> 2;
    const int wn = wid & 3;
    const int rowBase = blockIdx.y * 128;
    const int colBase = blockIdx.x * 128;
    const int nk = K >> 5;

    float acc[2][4][4];
#pragma unroll
    for (int i = 0; i < 2; i++)
#pragma unroll
        for (int j = 0; j < 4; j++)
#pragma unroll
            for (int c = 0; c < 4; c++) acc[i][j][c] = 0.f;

    float4 aR[2];
    uint4 bR[2];

    auto load_regs = [&](int t) {
#pragma unroll
        for (int i = 0; i < 2; i++) {
            int u = tid + i * 512;
            int r = u >> 3, q = u & 7;
            int grow = rowBase + r;
            aR[i] = make_float4(0.f, 0.f, 0.f, 0.f);
            if (grow < M) aR[i] = *(const float4*)(A + (size_t)grow * K + t * 32 + q * 4);
            bR[i] = *(const uint4*)(Bt + (size_t)(colBase + r) * K + t * 32 + q * 4);
        }
    };

    auto store_smem = [&](int s) {
        uint32_t* sA = smu + s * (2 * TSZ);
        uint32_t* sB = sA + TSZ;
#pragma unroll
        for (int i = 0; i < 2; i++) {
            int u = tid + i * 512;
            int r = u >> 3, q = u & 7;
            float4 va = aR[i];
            if (ELUA) {
                va.x = elu_f(va.x); va.y = elu_f(va.y);
                va.z = elu_f(va.z); va.w = elu_f(va.w);
            }
            uint4 ta = make_uint4(f2tf32(va.x), f2tf32(va.y), f2tf32(va.z), f2tf32(va.w));
            *(uint4*)&sA[r * SPF + q * 4] = ta;
            *(uint4*)&sB[r * SPF + q * 4] = bR[i];
        }
    };

    const int g = lane >> 2;
    const int t4 = lane & 3;

    auto compute = [&](int s) {
        const uint32_t* sA = smu + s * (2 * TSZ);
        const uint32_t* sB = sA + TSZ;
#pragma unroll
        for (int ks = 0; ks < 4; ks++) {
            int cb = ks * 8 + t4;
            uint32_t a[2][4];
#pragma unroll
            for (int mt = 0; mt < 2; mt++) {
                int rb = wm * 32 + mt * 16;
                a[mt][0] = sA[(rb + g) * SPF + cb];
                a[mt][1] = sA[(rb + g + 8) * SPF + cb];
                a[mt][2] = sA[(rb + g) * SPF + cb + 4];
                a[mt][3] = sA[(rb + g + 8) * SPF + cb + 4];
            }
            uint32_t b[4][2];
#pragma unroll
            for (int nt = 0; nt < 4; nt++) {
                int nb = wn * 32 + nt * 8 + g;
                b[nt][0] = sB[nb * SPF + cb];
                b[nt][1] = sB[nb * SPF + cb + 4];
            }
#pragma unroll
            for (int mt = 0; mt < 2; mt++)
#pragma unroll
                for (int nt = 0; nt < 4; nt++)
                    mma_tf32(acc[mt][nt], a[mt], b[nt]);
        }
    };

    load_regs(0);
    store_smem(0);
    __syncthreads();
    for (int t = 0; t < nk; t++) {
        if (t + 1 < nk) load_regs(t + 1);
        compute(t & 1);
        if (t + 1 < nk) store_smem((t + 1) & 1);
        __syncthreads();
    }

    const int t2 = (lane & 3) * 2;
#pragma unroll
    for (int mt = 0; mt < 2; mt++) {
        int row0 = rowBase + wm * 32 + mt * 16 + g;
#pragma unroll
        for (int nt = 0; nt < 4; nt++) {
            int col = colBase + wn * 32 + nt * 8 + t2;
            if (row0 < M)
                *(float2*)&C[(size_t)row0 * N + col] =
                    make_float2(acc[mt][nt][0], acc[mt][nt][1]);
            if (row0 + 8 < M)
                *(float2*)&C[(size_t)(row0 + 8) * N + col] =
                    make_float2(acc[mt][nt][2], acc[mt][nt][3]);
        }
    }

    if (ATT) {
#pragma unroll
        for (int mt = 0; mt < 2; mt++) {
            int row0 = rowBase + wm * 32 + mt * 16 + g;
            float sp0 = 0.f, sp1 = 0.f, dp0 = 0.f, dp1 = 0.f;
#pragma unroll
            for (int nt = 0; nt < 4; nt++) {
                int col = colBase + wn * 32 + nt * 8 + t2;
                float s0 = attS[col], s1 = attS[col + 1];
                float d0 = attD[col], d1 = attD[col + 1];
                sp0 += acc[mt][nt][0] * s0 + acc[mt][nt][1] * s1;
                sp1 += acc[mt][nt][2] * s0 + acc[mt][nt][3] * s1;
                dp0 += acc[mt][nt][0] * d0 + acc[mt][nt][1] * d1;
                dp1 += acc[mt][nt][2] * d0 + acc[mt][nt][3] * d1;
            }
#pragma unroll
            for (int o = 1; o <= 2; o <<= 1) {
                sp0 += __shfl_xor_sync(0xffffffffu, sp0, o);
                sp1 += __shfl_xor_sync(0xffffffffu, sp1, o);
                dp0 += __shfl_xor_sync(0xffffffffu, dp0, o);
                dp1 += __shfl_xor_sync(0xffffffffu, dp1, o);
            }
            if ((lane & 3) == 0) {
                if (row0 < M) {
                    atomicAdd(&a_s[row0], sp0);
                    atomicAdd(&a_d[row0], dp0);
                }
                if (row0 + 8 < M) {
                    atomicAdd(&a_s[row0 + 8], sp1);
                    atomicAdd(&a_d[row0 + 8], dp1);
                }
            }
        }
    }
}

// ---------------- fused GEMM2 + GEMM3 (tf32 single-pass) ------------------------------
// stage 1: h2[128,64] = elu(A[128,256]) @ B2t     (nk=8 double-buffered)
// stage 2: hp3[128,256] = h2 @ B3t                (K=64 smem-resident)
__global__ void __launch_bounds__(512)
gemm23_tf32(const float* __restrict__ A,
            const uint32_t* __restrict__ B2t, const uint32_t* __restrict__ B3t,
            float* __restrict__ H2, float* __restrict__ HP3, int M) {
    constexpr int SPF = 36;
    constexpr int ATSZ = 128 * SPF;        // 4608 words
    constexpr int BTSZ = 64 * SPF;         // 2304 words
    constexpr int SPF2 = 68;
    constexpr int HWORDS = 128 * SPF2;     // 8704 words
    // stage1: A tiles at [0, 2*ATSZ), B tiles at [2*ATSZ, 2*ATSZ+2*BTSZ)
    // stage2 (reuse): sH at [0, HWORDS), sB3 at [HWORDS, HWORDS+256*SPF2)

    extern __shared__ uint32_t smu[];

    const int tid = threadIdx.x;
    const int wid = tid >> 5;
    const int lane = tid & 31;
    const int rowBase = blockIdx.y * 128;

    const int g = lane >> 2;
    const int t4 = lane & 3;
    const int t2 = (lane & 3) * 2;

    // ---------------- stage 1 ----------------
    {
        const int wm = wid >> 2;   // 0..3, 32 rows
        const int wn = wid & 3;    // 0..3, 16 cols
        float acc1[2][2][4];
#pragma unroll
        for (int i = 0; i < 2; i++)
#pragma unroll
            for (int j = 0; j < 2; j++)
#pragma unroll
                for (int c = 0; c < 4; c++) acc1[i][j][c] = 0.f;

        float4 aR[2];
        uint4 bR;
        const int br = tid >> 3, bq = tid & 7;   // 512 uint4 slots for B (64 rows x 8)

        auto load1 = [&](int t) {
#pragma unroll
            for (int i = 0; i < 2; i++) {
                int u = tid + i * 512;
                int r = u >> 3, q = u & 7;
                int grow = rowBase + r;
                aR[i] = make_float4(0.f, 0.f, 0.f, 0.f);
                if (grow < M) aR[i] = *(const float4*)(A + (size_t)grow * 256 + t * 32 + q * 4);
            }
            bR = *(const uint4*)(B2t + (size_t)br * 256 + t * 32 + bq * 4);
        };
        auto store1 = [&](int s) {
            uint32_t* sA = smu + s * ATSZ;
            uint32_t* sB = smu + 2 * ATSZ + s * BTSZ;
#pragma unroll
            for (int i = 0; i < 2; i++) {
                int u = tid + i * 512;
                int r = u >> 3, q = u & 7;
                float4 v = aR[i];
                v.x = elu_f(v.x); v.y = elu_f(v.y);
                v.z = elu_f(v.z); v.w = elu_f(v.w);
                uint4 ta = make_uint4(f2tf32(v.x), f2tf32(v.y), f2tf32(v.z), f2tf32(v.w));
                *(uint4*)&sA[r * SPF + q * 4] = ta;
            }
            *(uint4*)&sB[br * SPF + bq * 4] = bR;
        };
        auto compute1 = [&](int s) {
            const uint32_t* sA = smu + s * ATSZ;
            const uint32_t* sB = smu + 2 * ATSZ + s * BTSZ;
#pragma unroll
            for (int ks = 0; ks < 4; ks++) {
                int cb = ks * 8 + t4;
                uint32_t a[2][4];
#pragma unroll
                for (int mt = 0; mt < 2; mt++) {
                    int rb = wm * 32 + mt * 16;
                    a[mt][0] = sA[(rb + g) * SPF + cb];
                    a[mt][1] = sA[(rb + g + 8) * SPF + cb];
                    a[mt][2] = sA[(rb + g) * SPF + cb + 4];
                    a[mt][3] = sA[(rb + g + 8) * SPF + cb + 4];
                }
                uint32_t b[2][2];
#pragma unroll
                for (int nt = 0; nt < 2; nt++) {
                    int nb = wn * 16 + nt * 8 + g;
                    b[nt][0] = sB[nb * SPF + cb];
                    b[nt][1] = sB[nb * SPF + cb + 4];
                }
#pragma unroll
                for (int mt = 0; mt < 2; mt++)
#pragma unroll
                    for (int nt = 0; nt < 2; nt++)
                        mma_tf32(acc1[mt][nt], a[mt], b[nt]);
            }
        };

        load1(0);
        store1(0);
        __syncthreads();
        for (int t = 0; t < 8; t++) {
            if (t + 1 < 8) load1(t + 1);
            compute1(t & 1);
            if (t + 1 < 8) store1((t + 1) & 1);
            __syncthreads();
        }

        // epilogue 1: write h2 to gmem + tf32 into sH (stage-2 A operand)
        uint32_t* sH = smu;
#pragma unroll
        for (int mt = 0; mt < 2; mt++) {
            int rl0 = wm * 32 + mt * 16 + g;
#pragma unroll
            for (int nt = 0; nt < 2; nt++) {
                int col = wn * 16 + nt * 8 + t2;
                float v0 = acc1[mt][nt][0], v1 = acc1[mt][nt][1];
                float v2 = acc1[mt][nt][2], v3 = acc1[mt][nt][3];
                int grow0 = rowBase + rl0;
                if (grow0 < M) *(float2*)&H2[(size_t)grow0 * 64 + col] = make_float2(v0, v1);
                if (grow0 + 8 < M) *(float2*)&H2[(size_t)(grow0 + 8) * 64 + col] = make_float2(v2, v3);
                sH[rl0 * SPF2 + col] = f2tf32(v0);
                sH[rl0 * SPF2 + col + 1] = f2tf32(v1);
                sH[(rl0 + 8) * SPF2 + col] = f2tf32(v2);
                sH[(rl0 + 8) * SPF2 + col + 1] = f2tf32(v3);
            }
        }
    }
    __syncthreads();

    // ---------------- stage 2 ----------------
    {
        uint32_t* sB3 = smu + HWORDS;
        // fill B3: 256 rows x 64 words = 4096 uint4, 8 per thread
#pragma unroll
        for (int i = 0; i < 8; i++) {
            int u = tid + i * 512;
            int r = u >> 4, q = u & 15;
            *(uint4*)&sB3[r * SPF2 + q * 4] = *(const uint4*)(B3t + r * 64 + q * 4);
        }
        __syncthreads();

        const int wm = wid >> 3;   // 0..1, 64 rows
        const int wn = wid & 7;    // 0..7, 32 cols
        float acc2[4][4][4];
#pragma unroll
        for (int i = 0; i < 4; i++)
#pragma unroll
            for (int j = 0; j < 4; j++)
#pragma unroll
                for (int c = 0; c < 4; c++) acc2[i][j][c] = 0.f;

        const uint32_t* sH = smu;
#pragma unroll
        for (int ks = 0; ks < 8; ks++) {
            int cb = ks * 8 + t4;
            uint32_t a[4][4];
#pragma unroll
            for (int mt = 0; mt < 4; mt++) {
                int rb = wm * 64 + mt * 16;
                a[mt][0] = sH[(rb + g) * SPF2 + cb];
                a[mt][1] = sH[(rb + g + 8) * SPF2 + cb];
                a[mt][2] = sH[(rb + g) * SPF2 + cb + 4];
                a[mt][3] = sH[(rb + g + 8) * SPF2 + cb + 4];
            }
            uint32_t b[4][2];
#pragma unroll
            for (int nt = 0; nt < 4; nt++) {
                int nb = wn * 32 + nt * 8 + g;
                b[nt][0] = sB3[nb * SPF2 + cb];
                b[nt][1] = sB3[nb * SPF2 + cb + 4];
            }
#pragma unroll
            for (int mt = 0; mt < 4; mt++)
#pragma unroll
                for (int nt = 0; nt < 4; nt++)
                    mma_tf32(acc2[mt][nt], a[mt], b[nt]);
        }

#pragma unroll
        for (int mt = 0; mt < 4; mt++) {
            int row0 = rowBase + wm * 64 + mt * 16 + g;
#pragma unroll
            for (int nt = 0; nt < 4; nt++) {
                int col = wn * 32 + nt * 8 + t2;
                if (row0 < M)
                    *(float2*)&HP3[(size_t)row0 * 256 + col] =
                        make_float2(acc2[mt][nt][0], acc2[mt][nt][1]);
                if (row0 + 8 < M)
                    *(float2*)&HP3[(size_t)(row0 + 8) * 256 + col] =
                        make_float2(acc2[mt][nt][2], acc2[mt][nt][3]);
            }
        }
    }
}

// ---------------- launch --------------------------------------------------------------
extern "C" void kernel_launch(void* const* d_in, const int* in_sizes, int n_in,
                              void* d_out, int out_size) {
    const float* features = (const float*)d_in[0];
    const float* W1       = (const float*)d_in[1];
    const float* W2       = (const float*)d_in[2];
    const float* att_src  = (const float*)d_in[3];
    const float* att_dst  = (const float*)d_in[4];
    const int*   edge     = (const int*)d_in[5];
    const int* src = edge;
    const int* dst = edge + E_EDGES;

    float* out = (float*)d_out;
    float* h2 = out;
    float* h4 = out + (size_t)N_NODES * OUT_DIM_;

    float *hp1, *h1acc, *hp3, *a_s, *a_d;
    cudaGetSymbolAddress((void**)&hp1,   g_hp1);
    cudaGetSymbolAddress((void**)&h1acc, g_h1acc);
    cudaGetSymbolAddress((void**)&hp3,   g_hp3);
    cudaGetSymbolAddress((void**)&a_s,   g_as);
    cudaGetSymbolAddress((void**)&a_d,   g_ad);

    int *deg, *start, *cursor, *csr_src;
    float* csr_w;
    cudaGetSymbolAddress((void**)&deg,     g_deg);
    cudaGetSymbolAddress((void**)&start,   g_start);
    cudaGetSymbolAddress((void**)&cursor,  g_cursor);
    cudaGetSymbolAddress((void**)&csr_src, g_csr_src);
    cudaGetSymbolAddress((void**)&csr_w,   g_csr_w);

    uint32_t *b1t, *b4t, *b2t, *b3t;
    cudaGetSymbolAddress((void**)&b1t, g_b1t);
    cudaGetSymbolAddress((void**)&b4t, g_b4t);
    cudaGetSymbolAddress((void**)&b2t, g_b2t);
    cudaGetSymbolAddress((void**)&b3t, g_b3t);

    const int smemTf = 2 * 2 * 128 * 36 * 4;                 // 73728
    const int smem23 = (128 * 68 + 256 * 68) * 4;            // 104448
    cudaFuncSetAttribute(tf32_gemm<false, true>,
                         cudaFuncAttributeMaxDynamicSharedMemorySize, smemTf);
    cudaFuncSetAttribute(tf32_gemm<true, false>,
                         cudaFuncAttributeMaxDynamicSharedMemorySize, smemTf);
    cudaFuncSetAttribute(gemm23_tf32,
                         cudaFuncAttributeMaxDynamicSharedMemorySize, smem23);

    const int mtiles = (N_NODES + 127) / 128;   // 391
    const int nodeWarpGrid = (N_NODES * 32 + 255) / 256;

    // fork: CSR build on s2, overlapped with prep + GEMM1 on main
    cudaStream_t s2;
    cudaStreamCreateWithFlags(&s2, cudaStreamNonBlocking);
    cudaEvent_t e1, e_csr;
    cudaEventCreateWithFlags(&e1,    cudaEventDisableTiming);
    cudaEventCreateWithFlags(&e_csr, cudaEventDisableTiming);

    cudaEventRecord(e1, 0);
    cudaStreamWaitEvent(s2, e1, 0);
    zero_deg<<<(N_NODES + 255) / 256, 256, 0, s2>>>(deg);
    count_deg<<<(E_EDGES + 255) / 256, 256, 0, s2>>>(dst, deg);
    scan_deg<<<1, 1024, 0, s2>>>(deg, start, cursor);
    fill_csr<<<(E_EDGES + 255) / 256, 256, 0, s2>>>(src, dst, cursor, csr_src);
    cudaEventRecord(e_csr, s2);

    // main chain
    prep_weights<<<(512 * 256 + 255) / 256, 256>>>(W1, W2, b1t, b4t, b2t, b3t, a_s, a_d);
    // GEMM1: hp1 = features @ W1  (tf32, fused attention dots)
    tf32_gemm<false, true><<<dim3(2, mtiles), 512, smemTf>>>(
        features, b1t, hp1, N_NODES, HID_, IN_DIM_, att_src, att_dst, a_s, a_d);

    cudaStreamWaitEvent(0, e_csr, 0);

    softmax_prop<<<nodeWarpGrid, 256>>>(start, deg, csr_src, a_s, a_d, csr_w, hp1, h1acc);
    gemm23_tf32<<<dim3(1, mtiles), 512, smem23>>>(h1acc, b2t, b3t, h2, hp3, N_NODES);
    propagate_csr<<<nodeWarpGrid, 256>>>(start, deg, csr_src, csr_w, hp3, h1acc);
    // GEMM4: h4 = elu(h1acc) @ W1^T  (tf32)
    tf32_gemm<true, false><<<dim3(4, mtiles), 512, smemTf>>>(
        h1acc, b4t, h4, N_NODES, IN_DIM_, HID_, nullptr, nullptr, nullptr, nullptr);

    (void)in_sizes; (void)n_in; (void)out_size;
}

// round 16
// speedup vs baseline: 1.0082x; 1.0082x over previous
#include <cuda_runtime.h>
#include <math.h>
#include <stdint.h>

#define N_NODES 50000
#define E_EDGES 600000
#define IN_DIM_ 512
#define HID_ 256
#define OUT_DIM_ 64

// ---------------- scratch (static device globals; no allocations) ----------
__device__ float g_hp1[(size_t)N_NODES * HID_];
__device__ float g_h1acc[(size_t)N_NODES * HID_];   // prop1 result; reused for prop2
__device__ float g_hp3[(size_t)N_NODES * HID_];
__device__ float g_as[N_NODES];
__device__ float g_ad[N_NODES];

// CSR by destination
__device__ int g_deg[N_NODES];
__device__ int g_start[N_NODES];
__device__ int g_cursor[N_NODES];
__device__ int g_csr_src[E_EDGES];
__device__ float g_csr_w[E_EDGES];

// prepped weights (all tf32, B[n][k] layout)
__device__ uint32_t g_b1t[256 * 512];               // W1^T  (N=256,K=512)
__device__ uint32_t g_b4t[512 * 256];               // W1    (N=512,K=256)
__device__ uint32_t g_b2t[64 * 256];                // W2^T  (N=64, K=256)
__device__ uint32_t g_b3t[256 * 64];                // W2    (N=256,K=64)

// ---------------- helpers -----------------------------------------------------
__device__ __forceinline__ float elu_f(float x) {
    return x > 0.f ? x : (expf(x) - 1.f);
}
__device__ __forceinline__ uint32_t f2tf32(float x) {
    uint32_t u;
    asm("cvt.rna.tf32.f32 %0, %1;" : "=r"(u) : "f"(x));
    return u;
}
__device__ __forceinline__ void mma_tf32(float* d, const uint32_t* a, const uint32_t* b) {
    asm volatile(
        "mma.sync.aligned.m16n8k8.row.col.f32.tf32.tf32.f32 "
        "{%0,%1,%2,%3}, {%4,%5,%6,%7}, {%8,%9}, {%0,%1,%2,%3};"
        : "+f"(d[0]), "+f"(d[1]), "+f"(d[2]), "+f"(d[3])
        : "r"(a[0]), "r"(a[1]), "r"(a[2]), "r"(a[3]), "r"(b[0]), "r"(b[1]));
}

// ---------------- CSR build ----------------------------------------------------
__global__ void zero_deg(int* deg) {
    int i = blockIdx.x * blockDim.x + threadIdx.x;
    if (i < N_NODES) deg[i] = 0;
}

__global__ void count_deg(const int* __restrict__ dst, int* __restrict__ deg) {
    int e = blockIdx.x * blockDim.x + threadIdx.x;
    if (e < E_EDGES) atomicAdd(&deg[dst[e]], 1);
}

__global__ void scan_deg(const int* __restrict__ deg, int* __restrict__ start,
                         int* __restrict__ cursor) {
    __shared__ int warp_sums[32];
    __shared__ int s_carry;
    if (threadIdx.x == 0) s_carry = 0;
    __syncthreads();
    const int tid = threadIdx.x;
    const int lane = tid & 31;
    const int wid = tid >> 5;
    for (int base = 0; base < N_NODES; base += 1024) {
        int i = base + tid;
        int v = (i < N_NODES) ? deg[i] : 0;
        int incl = v;
#pragma unroll
        for (int o = 1; o < 32; o <<= 1) {
            int t = __shfl_up_sync(0xffffffffu, incl, o);
            if (lane >= o) incl += t;
        }
        if (lane == 31) warp_sums[wid] = incl;
        __syncthreads();
        if (wid == 0) {
            int ws = warp_sums[lane];
            int wincl = ws;
#pragma unroll
            for (int o = 1; o < 32; o <<= 1) {
                int t = __shfl_up_sync(0xffffffffu, wincl, o);
                if (lane >= o) wincl += t;
            }
            warp_sums[lane] = wincl - ws;
        }
        __syncthreads();
        int excl = incl - v + warp_sums[wid] + s_carry;
        if (i < N_NODES) { start[i] = excl; cursor[i] = excl; }
        __syncthreads();
        if (tid == 1023) s_carry = excl + v;
        __syncthreads();
    }
}

__global__ void fill_csr(const int* __restrict__ src, const int* __restrict__ dst,
                         int* __restrict__ cursor, int* __restrict__ csr_src) {
    int e = blockIdx.x * blockDim.x + threadIdx.x;
    if (e >= E_EDGES) return;
    int pos = atomicAdd(&cursor[dst[e]], 1);
    csr_src[pos] = src[e];
}

// ---------------- fused softmax + propagate-1 (warp per dst) --------------------
__global__ void __launch_bounds__(256)
softmax_prop(const int* __restrict__ start, const int* __restrict__ deg,
             const int* __restrict__ csr_src,
             const float* __restrict__ a_s, const float* __restrict__ a_d,
             float* __restrict__ csr_w,
             const float* __restrict__ H, float* __restrict__ out) {
    int d = (blockIdx.x * blockDim.x + threadIdx.x) >> 5;
    int lane = threadIdx.x & 31;
    if (d >= N_NODES) return;
    int s0 = start[d], n = deg[d];

    float4 acc0 = make_float4(0.f, 0.f, 0.f, 0.f);
    float4 acc1 = make_float4(0.f, 0.f, 0.f, 0.f);

    if (n > 0 && n <= 64) {
        float ad = a_d[d];
        int se0 = 0, se1 = 0;
        float l0 = -INFINITY, l1 = -INFINITY;
        if (lane < n) {
            se0 = csr_src[s0 + lane];
            float x = a_s[se0] + ad;
            l0 = x > 0.f ? x : 0.2f * x;
        }
        if (lane + 32 < n) {
            se1 = csr_src[s0 + lane + 32];
            float x = a_s[se1] + ad;
            l1 = x > 0.f ? x : 0.2f * x;
        }
        float mx = fmaxf(l0, l1);
#pragma unroll
        for (int o = 16; o; o >>= 1) mx = fmaxf(mx, __shfl_xor_sync(0xffffffffu, mx, o));
        float w0 = (lane < n) ? expf(l0 - mx) : 0.f;
        float w1 = (lane + 32 < n) ? expf(l1 - mx) : 0.f;
        float sum = w0 + w1;
#pragma unroll
        for (int o = 16; o; o >>= 1) sum += __shfl_xor_sync(0xffffffffu, sum, o);
        float inv = 1.f / (sum + 1e-16f);
        w0 *= inv; w1 *= inv;
        if (lane < n) csr_w[s0 + lane] = w0;
        if (lane + 32 < n) csr_w[s0 + lane + 32] = w1;

        for (int i = 0; i < n; i++) {
            int si; float wi;
            if (i < 32) {
                si = __shfl_sync(0xffffffffu, se0, i);
                wi = __shfl_sync(0xffffffffu, w0, i);
            } else {
                si = __shfl_sync(0xffffffffu, se1, i - 32);
                wi = __shfl_sync(0xffffffffu, w1, i - 32);
            }
            const float4* r = (const float4*)(H + (size_t)si * HID_);
            float4 v0 = r[lane], v1 = r[lane + 32];
            acc0.x = fmaf(v0.x, wi, acc0.x); acc0.y = fmaf(v0.y, wi, acc0.y);
            acc0.z = fmaf(v0.z, wi, acc0.z); acc0.w = fmaf(v0.w, wi, acc0.w);
            acc1.x = fmaf(v1.x, wi, acc1.x); acc1.y = fmaf(v1.y, wi, acc1.y);
            acc1.z = fmaf(v1.z, wi, acc1.z); acc1.w = fmaf(v1.w, wi, acc1.w);
        }
    } else if (n > 64) {
        float ad = a_d[d];
        float mx = -INFINITY;
        for (int i = lane; i < n; i += 32) {
            float x = a_s[csr_src[s0 + i]] + ad;
            x = x > 0.f ? x : 0.2f * x;
            csr_w[s0 + i] = x;
            mx = fmaxf(mx, x);
        }
#pragma unroll
        for (int o = 16; o; o >>= 1) mx = fmaxf(mx, __shfl_xor_sync(0xffffffffu, mx, o));
        float sum = 0.f;
        for (int i = lane; i < n; i += 32) {
            float ex = expf(csr_w[s0 + i] - mx);
            csr_w[s0 + i] = ex;
            sum += ex;
        }
#pragma unroll
        for (int o = 16; o; o >>= 1) sum += __shfl_xor_sync(0xffffffffu, sum, o);
        float inv = 1.f / (sum + 1e-16f);
        for (int i = lane; i < n; i += 32) csr_w[s0 + i] *= inv;
        __threadfence_block();
        __syncwarp();
        for (int i = 0; i < n; i++) {
            int si = csr_src[s0 + i];
            float wi = csr_w[s0 + i];
            const float4* r = (const float4*)(H + (size_t)si * HID_);
            float4 v0 = r[lane], v1 = r[lane + 32];
            acc0.x = fmaf(v0.x, wi, acc0.x); acc0.y = fmaf(v0.y, wi, acc0.y);
            acc0.z = fmaf(v0.z, wi, acc0.z); acc0.w = fmaf(v0.w, wi, acc0.w);
            acc1.x = fmaf(v1.x, wi, acc1.x); acc1.y = fmaf(v1.y, wi, acc1.y);
            acc1.z = fmaf(v1.z, wi, acc1.z); acc1.w = fmaf(v1.w, wi, acc1.w);
        }
    }
    float4* orow = (float4*)(out + (size_t)d * HID_);
    orow[lane] = acc0;
    orow[lane + 32] = acc1;
}

// ---------------- propagate-2: register-resident indices/weights ----------------------
__global__ void __launch_bounds__(256)
propagate_csr(const int* __restrict__ start, const int* __restrict__ deg,
              const int* __restrict__ csr_src, const float* __restrict__ csr_w,
              const float* __restrict__ H, float* __restrict__ out) {
    int d = (blockIdx.x * blockDim.x + threadIdx.x) >> 5;
    int lane = threadIdx.x & 31;
    if (d >= N_NODES) return;
    int s0 = start[d], n = deg[d];
    float4 acc0 = make_float4(0.f, 0.f, 0.f, 0.f);
    float4 acc1 = make_float4(0.f, 0.f, 0.f, 0.f);

    if (n > 0 && n <= 64) {
        // preload (src, w) into registers; broadcast in gather loop (no in-loop loads)
        int se0 = 0, se1 = 0;
        float w0 = 0.f, w1 = 0.f;
        if (lane < n) { se0 = csr_src[s0 + lane]; w0 = csr_w[s0 + lane]; }
        if (lane + 32 < n) { se1 = csr_src[s0 + lane + 32]; w1 = csr_w[s0 + lane + 32]; }
        int i = 0;
        for (; i + 2 <= n; i += 2) {
            int sA, sB; float wA, wB;
            if (i < 32) { sA = __shfl_sync(0xffffffffu, se0, i); wA = __shfl_sync(0xffffffffu, w0, i); }
            else        { sA = __shfl_sync(0xffffffffu, se1, i - 32); wA = __shfl_sync(0xffffffffu, w1, i - 32); }
            int j = i + 1;
            if (j < 32) { sB = __shfl_sync(0xffffffffu, se0, j); wB = __shfl_sync(0xffffffffu, w0, j); }
            else        { sB = __shfl_sync(0xffffffffu, se1, j - 32); wB = __shfl_sync(0xffffffffu, w1, j - 32); }
            const float4* rA = (const float4*)(H + (size_t)sA * HID_);
            const float4* rB = (const float4*)(H + (size_t)sB * HID_);
            float4 a0 = rA[lane], a1 = rA[lane + 32];
            float4 b0 = rB[lane], b1 = rB[lane + 32];
            acc0.x = fmaf(a0.x, wA, acc0.x); acc0.y = fmaf(a0.y, wA, acc0.y);
            acc0.z = fmaf(a0.z, wA, acc0.z); acc0.w = fmaf(a0.w, wA, acc0.w);
            acc1.x = fmaf(a1.x, wA, acc1.x); acc1.y = fmaf(a1.y, wA, acc1.y);
            acc1.z = fmaf(a1.z, wA, acc1.z); acc1.w = fmaf(a1.w, wA, acc1.w);
            acc0.x = fmaf(b0.x, wB, acc0.x); acc0.y = fmaf(b0.y, wB, acc0.y);
            acc0.z = fmaf(b0.z, wB, acc0.z); acc0.w = fmaf(b0.w, wB, acc0.w);
            acc1.x = fmaf(b1.x, wB, acc1.x); acc1.y = fmaf(b1.y, wB, acc1.y);
            acc1.z = fmaf(b1.z, wB, acc1.z); acc1.w = fmaf(b1.w, wB, acc1.w);
        }
        if (i < n) {
            int sA; float wA;
            if (i < 32) { sA = __shfl_sync(0xffffffffu, se0, i); wA = __shfl_sync(0xffffffffu, w0, i); }
            else        { sA = __shfl_sync(0xffffffffu, se1, i - 32); wA = __shfl_sync(0xffffffffu, w1, i - 32); }
            const float4* r = (const float4*)(H + (size_t)sA * HID_);
            float4 a0 = r[lane], a1 = r[lane + 32];
            acc0.x = fmaf(a0.x, wA, acc0.x); acc0.y = fmaf(a0.y, wA, acc0.y);
            acc0.z = fmaf(a0.z, wA, acc0.z); acc0.w = fmaf(a0.w, wA, acc0.w);
            acc1.x = fmaf(a1.x, wA, acc1.x); acc1.y = fmaf(a1.y, wA, acc1.y);
            acc1.z = fmaf(a1.z, wA, acc1.z); acc1.w = fmaf(a1.w, wA, acc1.w);
        }
    } else if (n > 64) {
        int i = 0;
        for (; i + 2 <= n; i += 2) {
            int sA = csr_src[s0 + i], sB = csr_src[s0 + i + 1];
            float wA = csr_w[s0 + i], wB = csr_w[s0 + i + 1];
            const float4* rA = (const float4*)(H + (size_t)sA * HID_);
            const float4* rB = (const float4*)(H + (size_t)sB * HID_);
            float4 a0 = rA[lane], a1 = rA[lane + 32];
            float4 b0 = rB[lane], b1 = rB[lane + 32];
            acc0.x = fmaf(a0.x, wA, acc0.x); acc0.y = fmaf(a0.y, wA, acc0.y);
            acc0.z = fmaf(a0.z, wA, acc0.z); acc0.w = fmaf(a0.w, wA, acc0.w);
            acc1.x = fmaf(a1.x, wA, acc1.x); acc1.y = fmaf(a1.y, wA, acc1.y);
            acc1.z = fmaf(a1.z, wA, acc1.z); acc1.w = fmaf(a1.w, wA, acc1.w);
            acc0.x = fmaf(b0.x, wB, acc0.x); acc0.y = fmaf(b0.y, wB, acc0.y);
            acc0.z = fmaf(b0.z, wB, acc0.z); acc0.w = fmaf(b0.w, wB, acc0.w);
            acc1.x = fmaf(b1.x, wB, acc1.x); acc1.y = fmaf(b1.y, wB, acc1.y);
            acc1.z = fmaf(b1.z, wB, acc1.z); acc1.w = fmaf(b1.w, wB, acc1.w);
        }
        if (i < n) {
            int s = csr_src[s0 + i];
            float w = csr_w[s0 + i];
            const float4* r = (const float4*)(H + (size_t)s * HID_);
            float4 a0 = r[lane], a1 = r[lane + 32];
            acc0.x = fmaf(a0.x, w, acc0.x); acc0.y = fmaf(a0.y, w, acc0.y);
            acc0.z = fmaf(a0.z, w, acc0.z); acc0.w = fmaf(a0.w, w, acc0.w);
            acc1.x = fmaf(a1.x, w, acc1.x); acc1.y = fmaf(a1.y, w, acc1.y);
            acc1.z = fmaf(a1.z, w, acc1.z); acc1.w = fmaf(a1.w, w, acc1.w);
        }
    }
    float4* orow = (float4*)(out + (size_t)d * HID_);
    orow[lane] = acc0;
    orow[lane + 32] = acc1;
}

// ---------------- weight prep (all tf32, + zero a_s/a_d) -----------------------------
__global__ void prep_weights(const float* __restrict__ W1, const float* __restrict__ W2,
                             uint32_t* b1t, uint32_t* b4t,
                             uint32_t* b2t, uint32_t* b3t,
                             float* a_s, float* a_d) {
    int i = blockIdx.x * blockDim.x + threadIdx.x;
    if (i < N_NODES) { a_s[i] = 0.f; a_d[i] = 0.f; }
    if (i < 512 * 256) {
        int k = i >> 8, n = i & 255;
        uint32_t t = f2tf32(W1[i]);
        b4t[i] = t;
        b1t[n * 512 + k] = t;
    }
    if (i < 256 * 64) {
        int k = i >> 6, n = i & 63;
        uint32_t t = f2tf32(W2[i]);
        b3t[i] = t;
        b2t[n * 256 + k] = t;
    }
}

// ---------------- unified tf32 GEMM (straight layout, conflict-free) -----------------
template <bool ELUA, bool ATT>
__global__ void __launch_bounds__(512)
tf32_gemm(const float* __restrict__ A, const uint32_t* __restrict__ Bt,
          float* __restrict__ C, int M, int N, int K,
          const float* __restrict__ attS, const float* __restrict__ attD,
          float* __restrict__ a_s, float* __restrict__ a_d) {
    constexpr int SPF = 36;
    constexpr int TSZ = 128 * SPF;

    extern __shared__ uint32_t smu[];

    const int tid = threadIdx.x;
    const int wid = tid >> 5;
    const int lane = tid & 31;
    const int wm = wid >> 2;
    const int wn = wid & 3;
    const int rowBase = blockIdx.y * 128;
    const int colBase = blockIdx.x * 128;
    const int nk = K >> 5;

    float acc[2][4][4];
#pragma unroll
    for (int i = 0; i < 2; i++)
#pragma unroll
        for (int j = 0; j < 4; j++)
#pragma unroll
            for (int c = 0; c < 4; c++) acc[i][j][c] = 0.f;

    float4 aR[2];
    uint4 bR[2];

    auto load_regs = [&](int t) {
#pragma unroll
        for (int i = 0; i < 2; i++) {
            int u = tid + i * 512;
            int r = u >> 3, q = u & 7;
            int grow = rowBase + r;
            aR[i] = make_float4(0.f, 0.f, 0.f, 0.f);
            if (grow < M) aR[i] = *(const float4*)(A + (size_t)grow * K + t * 32 + q * 4);
            bR[i] = *(const uint4*)(Bt + (size_t)(colBase + r) * K + t * 32 + q * 4);
        }
    };

    auto store_smem = [&](int s) {
        uint32_t* sA = smu + s * (2 * TSZ);
        uint32_t* sB = sA + TSZ;
#pragma unroll
        for (int i = 0; i < 2; i++) {
            int u = tid + i * 512;
            int r = u >> 3, q = u & 7;
            float4 va = aR[i];
            if (ELUA) {
                va.x = elu_f(va.x); va.y = elu_f(va.y);
                va.z = elu_f(va.z); va.w = elu_f(va.w);
            }
            uint4 ta = make_uint4(f2tf32(va.x), f2tf32(va.y), f2tf32(va.z), f2tf32(va.w));
            *(uint4*)&sA[r * SPF + q * 4] = ta;
            *(uint4*)&sB[r * SPF + q * 4] = bR[i];
        }
    };

    const int g = lane >> 2;
    const int t4 = lane & 3;

    auto compute = [&](int s) {
        const uint32_t* sA = smu + s * (2 * TSZ);
        const uint32_t* sB = sA + TSZ;
#pragma unroll
        for (int ks = 0; ks < 4; ks++) {
            int cb = ks * 8 + t4;
            uint32_t a[2][4];
#pragma unroll
            for (int mt = 0; mt < 2; mt++) {
                int rb = wm * 32 + mt * 16;
                a[mt][0] = sA[(rb + g) * SPF + cb];
                a[mt][1] = sA[(rb + g + 8) * SPF + cb];
                a[mt][2] = sA[(rb + g) * SPF + cb + 4];
                a[mt][3] = sA[(rb + g + 8) * SPF + cb + 4];
            }
            uint32_t b[4][2];
#pragma unroll
            for (int nt = 0; nt < 4; nt++) {
                int nb = wn * 32 + nt * 8 + g;
                b[nt][0] = sB[nb * SPF + cb];
                b[nt][1] = sB[nb * SPF + cb + 4];
            }
#pragma unroll
            for (int mt = 0; mt < 2; mt++)
#pragma unroll
                for (int nt = 0; nt < 4; nt++)
                    mma_tf32(acc[mt][nt], a[mt], b[nt]);
        }
    };

    load_regs(0);
    store_smem(0);
    __syncthreads();
    for (int t = 0; t < nk; t++) {
        if (t + 1 < nk) load_regs(t + 1);
        compute(t & 1);
        if (t + 1 < nk) store_smem((t + 1) & 1);
        __syncthreads();
    }

    const int t2 = (lane & 3) * 2;
#pragma unroll
    for (int mt = 0; mt < 2; mt++) {
        int row0 = rowBase + wm * 32 + mt * 16 + g;
#pragma unroll
        for (int nt = 0; nt < 4; nt++) {
            int col = colBase + wn * 32 + nt * 8 + t2;
            if (row0 < M)
                *(float2*)&C[(size_t)row0 * N + col] =
                    make_float2(acc[mt][nt][0], acc[mt][nt][1]);
            if (row0 + 8 < M)
                *(float2*)&C[(size_t)(row0 + 8) * N + col] =
                    make_float2(acc[mt][nt][2], acc[mt][nt][3]);
        }
    }

    if (ATT) {
#pragma unroll
        for (int mt = 0; mt < 2; mt++) {
            int row0 = rowBase + wm * 32 + mt * 16 + g;
            float sp0 = 0.f, sp1 = 0.f, dp0 = 0.f, dp1 = 0.f;
#pragma unroll
            for (int nt = 0; nt < 4; nt++) {
                int col = colBase + wn * 32 + nt * 8 + t2;
                float s0 = attS[col], s1 = attS[col + 1];
                float d0 = attD[col], d1 = attD[col + 1];
                sp0 += acc[mt][nt][0] * s0 + acc[mt][nt][1] * s1;
                sp1 += acc[mt][nt][2] * s0 + acc[mt][nt][3] * s1;
                dp0 += acc[mt][nt][0] * d0 + acc[mt][nt][1] * d1;
                dp1 += acc[mt][nt][2] * d0 + acc[mt][nt][3] * d1;
            }
#pragma unroll
            for (int o = 1; o <= 2; o <<= 1) {
                sp0 += __shfl_xor_sync(0xffffffffu, sp0, o);
                sp1 += __shfl_xor_sync(0xffffffffu, sp1, o);
                dp0 += __shfl_xor_sync(0xffffffffu, dp0, o);
                dp1 += __shfl_xor_sync(0xffffffffu, dp1, o);
            }
            if ((lane & 3) == 0) {
                if (row0 < M) {
                    atomicAdd(&a_s[row0], sp0);
                    atomicAdd(&a_d[row0], dp0);
                }
                if (row0 + 8 < M) {
                    atomicAdd(&a_s[row0 + 8], sp1);
                    atomicAdd(&a_d[row0 + 8], dp1);
                }
            }
        }
    }
}

// ---------------- fused GEMM2 + GEMM3 (tf32 single-pass) ------------------------------
__global__ void __launch_bounds__(512)
gemm23_tf32(const float* __restrict__ A,
            const uint32_t* __restrict__ B2t, const uint32_t* __restrict__ B3t,
            float* __restrict__ H2, float* __restrict__ HP3, int M) {
    constexpr int SPF = 36;
    constexpr int ATSZ = 128 * SPF;
    constexpr int BTSZ = 64 * SPF;
    constexpr int SPF2 = 68;
    constexpr int HWORDS = 128 * SPF2;

    extern __shared__ uint32_t smu[];

    const int tid = threadIdx.x;
    const int wid = tid >> 5;
    const int lane = tid & 31;
    const int rowBase = blockIdx.y * 128;

    const int g = lane >> 2;
    const int t4 = lane & 3;
    const int t2 = (lane & 3) * 2;

    // stage 1
    {
        const int wm = wid >> 2;
        const int wn = wid & 3;
        float acc1[2][2][4];
#pragma unroll
        for (int i = 0; i < 2; i++)
#pragma unroll
            for (int j = 0; j < 2; j++)
#pragma unroll
                for (int c = 0; c < 4; c++) acc1[i][j][c] = 0.f;

        float4 aR[2];
        uint4 bR;
        const int br = tid >> 3, bq = tid & 7;

        auto load1 = [&](int t) {
#pragma unroll
            for (int i = 0; i < 2; i++) {
                int u = tid + i * 512;
                int r = u >> 3, q = u & 7;
                int grow = rowBase + r;
                aR[i] = make_float4(0.f, 0.f, 0.f, 0.f);
                if (grow < M) aR[i] = *(const float4*)(A + (size_t)grow * 256 + t * 32 + q * 4);
            }
            bR = *(const uint4*)(B2t + (size_t)br * 256 + t * 32 + bq * 4);
        };
        auto store1 = [&](int s) {
            uint32_t* sA = smu + s * ATSZ;
            uint32_t* sB = smu + 2 * ATSZ + s * BTSZ;
#pragma unroll
            for (int i = 0; i < 2; i++) {
                int u = tid + i * 512;
                int r = u >> 3, q = u & 7;
                float4 v = aR[i];
                v.x = elu_f(v.x); v.y = elu_f(v.y);
                v.z = elu_f(v.z); v.w = elu_f(v.w);
                uint4 ta = make_uint4(f2tf32(v.x), f2tf32(v.y), f2tf32(v.z), f2tf32(v.w));
                *(uint4*)&sA[r * SPF + q * 4] = ta;
            }
            *(uint4*)&sB[br * SPF + bq * 4] = bR;
        };
        auto compute1 = [&](int s) {
            const uint32_t* sA = smu + s * ATSZ;
            const uint32_t* sB = smu + 2 * ATSZ + s * BTSZ;
#pragma unroll
            for (int ks = 0; ks < 4; ks++) {
                int cb = ks * 8 + t4;
                uint32_t a[2][4];
#pragma unroll
                for (int mt = 0; mt < 2; mt++) {
                    int rb = wm * 32 + mt * 16;
                    a[mt][0] = sA[(rb + g) * SPF + cb];
                    a[mt][1] = sA[(rb + g + 8) * SPF + cb];
                    a[mt][2] = sA[(rb + g) * SPF + cb + 4];
                    a[mt][3] = sA[(rb + g + 8) * SPF + cb + 4];
                }
                uint32_t b[2][2];
#pragma unroll
                for (int nt = 0; nt < 2; nt++) {
                    int nb = wn * 16 + nt * 8 + g;
                    b[nt][0] = sB[nb * SPF + cb];
                    b[nt][1] = sB[nb * SPF + cb + 4];
                }
#pragma unroll
                for (int mt = 0; mt < 2; mt++)
#pragma unroll
                    for (int nt = 0; nt < 2; nt++)
                        mma_tf32(acc1[mt][nt], a[mt], b[nt]);
            }
        };

        load1(0);
        store1(0);
        __syncthreads();
        for (int t = 0; t < 8; t++) {
            if (t + 1 < 8) load1(t + 1);
            compute1(t & 1);
            if (t + 1 < 8) store1((t + 1) & 1);
            __syncthreads();
        }

        uint32_t* sH = smu;
#pragma unroll
        for (int mt = 0; mt < 2; mt++) {
            int rl0 = wm * 32 + mt * 16 + g;
#pragma unroll
            for (int nt = 0; nt < 2; nt++) {
                int col = wn * 16 + nt * 8 + t2;
                float v0 = acc1[mt][nt][0], v1 = acc1[mt][nt][1];
                float v2 = acc1[mt][nt][2], v3 = acc1[mt][nt][3];
                int grow0 = rowBase + rl0;
                if (grow0 < M) *(float2*)&H2[(size_t)grow0 * 64 + col] = make_float2(v0, v1);
                if (grow0 + 8 < M) *(float2*)&H2[(size_t)(grow0 + 8) * 64 + col] = make_float2(v2, v3);
                sH[rl0 * SPF2 + col] = f2tf32(v0);
                sH[rl0 * SPF2 + col + 1] = f2tf32(v1);
                sH[(rl0 + 8) * SPF2 + col] = f2tf32(v2);
                sH[(rl0 + 8) * SPF2 + col + 1] = f2tf32(v3);
            }
        }
    }
    __syncthreads();

    // stage 2
    {
        uint32_t* sB3 = smu + HWORDS;
#pragma unroll
        for (int i = 0; i < 8; i++) {
            int u = tid + i * 512;
            int r = u >> 4, q = u & 15;
            *(uint4*)&sB3[r * SPF2 + q * 4] = *(const uint4*)(B3t + r * 64 + q * 4);
        }
        __syncthreads();

        const int wm = wid >> 3;
        const int wn = wid & 7;
        float acc2[4][4][4];
#pragma unroll
        for (int i = 0; i < 4; i++)
#pragma unroll
            for (int j = 0; j < 4; j++)
#pragma unroll
                for (int c = 0; c < 4; c++) acc2[i][j][c] = 0.f;

        const uint32_t* sH = smu;
#pragma unroll
        for (int ks = 0; ks < 8; ks++) {
            int cb = ks * 8 + t4;
            uint32_t a[4][4];
#pragma unroll
            for (int mt = 0; mt < 4; mt++) {
                int rb = wm * 64 + mt * 16;
                a[mt][0] = sH[(rb + g) * SPF2 + cb];
                a[mt][1] = sH[(rb + g + 8) * SPF2 + cb];
                a[mt][2] = sH[(rb + g) * SPF2 + cb + 4];
                a[mt][3] = sH[(rb + g + 8) * SPF2 + cb + 4];
            }
            uint32_t b[4][2];
#pragma unroll
            for (int nt = 0; nt < 4; nt++) {
                int nb = wn * 32 + nt * 8 + g;
                b[nt][0] = sB3[nb * SPF2 + cb];
                b[nt][1] = sB3[nb * SPF2 + cb + 4];
            }
#pragma unroll
            for (int mt = 0; mt < 4; mt++)
#pragma unroll
                for (int nt = 0; nt < 4; nt++)
                    mma_tf32(acc2[mt][nt], a[mt], b[nt]);
        }

#pragma unroll
        for (int mt = 0; mt < 4; mt++) {
            int row0 = rowBase + wm * 64 + mt * 16 + g;
#pragma unroll
            for (int nt = 0; nt < 4; nt++) {
                int col = wn * 32 + nt * 8 + t2;
                if (row0 < M)
                    *(float2*)&HP3[(size_t)row0 * 256 + col] =
                        make_float2(acc2[mt][nt][0], acc2[mt][nt][1]);
                if (row0 + 8 < M)
                    *(float2*)&HP3[(size_t)(row0 + 8) * 256 + col] =
                        make_float2(acc2[mt][nt][2], acc2[mt][nt][3]);
            }
        }
    }
}

// ---------------- launch --------------------------------------------------------------
extern "C" void kernel_launch(void* const* d_in, const int* in_sizes, int n_in,
                              void* d_out, int out_size) {
    const float* features = (const float*)d_in[0];
    const float* W1       = (const float*)d_in[1];
    const float* W2       = (const float*)d_in[2];
    const float* att_src  = (const float*)d_in[3];
    const float* att_dst  = (const float*)d_in[4];
    const int*   edge     = (const int*)d_in[5];
    const int* src = edge;
    const int* dst = edge + E_EDGES;

    float* out = (float*)d_out;
    float* h2 = out;
    float* h4 = out + (size_t)N_NODES * OUT_DIM_;

    float *hp1, *h1acc, *hp3, *a_s, *a_d;
    cudaGetSymbolAddress((void**)&hp1,   g_hp1);
    cudaGetSymbolAddress((void**)&h1acc, g_h1acc);
    cudaGetSymbolAddress((void**)&hp3,   g_hp3);
    cudaGetSymbolAddress((void**)&a_s,   g_as);
    cudaGetSymbolAddress((void**)&a_d,   g_ad);

    int *deg, *start, *cursor, *csr_src;
    float* csr_w;
    cudaGetSymbolAddress((void**)&deg,     g_deg);
    cudaGetSymbolAddress((void**)&start,   g_start);
    cudaGetSymbolAddress((void**)&cursor,  g_cursor);
    cudaGetSymbolAddress((void**)&csr_src, g_csr_src);
    cudaGetSymbolAddress((void**)&csr_w,   g_csr_w);

    uint32_t *b1t, *b4t, *b2t, *b3t;
    cudaGetSymbolAddress((void**)&b1t, g_b1t);
    cudaGetSymbolAddress((void**)&b4t, g_b4t);
    cudaGetSymbolAddress((void**)&b2t, g_b2t);
    cudaGetSymbolAddress((void**)&b3t, g_b3t);

    const int smemTf = 2 * 2 * 128 * 36 * 4;                 // 73728
    const int smem23 = (128 * 68 + 256 * 68) * 4;            // 104448
    cudaFuncSetAttribute(tf32_gemm<false, true>,
                         cudaFuncAttributeMaxDynamicSharedMemorySize, smemTf);
    cudaFuncSetAttribute(tf32_gemm<true, false>,
                         cudaFuncAttributeMaxDynamicSharedMemorySize, smemTf);
    cudaFuncSetAttribute(gemm23_tf32,
                         cudaFuncAttributeMaxDynamicSharedMemorySize, smem23);

    const int mtiles = (N_NODES + 127) / 128;   // 391
    const int nodeWarpGrid = (N_NODES * 32 + 255) / 256;

    // fork: CSR build on s2, overlapped with prep + GEMM1 on main
    cudaStream_t s2;
    cudaStreamCreateWithFlags(&s2, cudaStreamNonBlocking);
    cudaEvent_t e1, e_csr;
    cudaEventCreateWithFlags(&e1,    cudaEventDisableTiming);
    cudaEventCreateWithFlags(&e_csr, cudaEventDisableTiming);

    cudaEventRecord(e1, 0);
    cudaStreamWaitEvent(s2, e1, 0);
    zero_deg<<<(N_NODES + 255) / 256, 256, 0, s2>>>(deg);
    count_deg<<<(E_EDGES + 255) / 256, 256, 0, s2>>>(dst, deg);
    scan_deg<<<1, 1024, 0, s2>>>(deg, start, cursor);
    fill_csr<<<(E_EDGES + 255) / 256, 256, 0, s2>>>(src, dst, cursor, csr_src);
    cudaEventRecord(e_csr, s2);

    // main chain
    prep_weights<<<(512 * 256 + 255) / 256, 256>>>(W1, W2, b1t, b4t, b2t, b3t, a_s, a_d);
    tf32_gemm<false, true><<<dim3(2, mtiles), 512, smemTf>>>(
        features, b1t, hp1, N_NODES, HID_, IN_DIM_, att_src, att_dst, a_s, a_d);

    cudaStreamWaitEvent(0, e_csr, 0);

    softmax_prop<<<nodeWarpGrid, 256>>>(start, deg, csr_src, a_s, a_d, csr_w, hp1, h1acc);
    gemm23_tf32<<<dim3(1, mtiles), 512, smem23>>>(h1acc, b2t, b3t, h2, hp3, N_NODES);
    propagate_csr<<<nodeWarpGrid, 256>>>(start, deg, csr_src, csr_w, hp3, h1acc);
    tf32_gemm<true, false><<<dim3(4, mtiles), 512, smemTf>>>(
        h1acc, b4t, h4, N_NODES, IN_DIM_, HID_, nullptr, nullptr, nullptr, nullptr);

    (void)in_sizes; (void)n_in; (void)out_size;
}

// round 17
// speedup vs baseline: 1.0295x; 1.0211x over previous
#include <cuda_runtime.h>
#include <cuda_fp16.h>
#include <math.h>
#include <stdint.h>

#define N_NODES 50000
#define E_EDGES 600000
#define IN_DIM_ 512
#define HID_ 256
#define OUT_DIM_ 64

// ---------------- scratch (static device globals; no allocations) ----------
__device__ __half g_hp1h[(size_t)N_NODES * HID_];   // GEMM1 out, fp16 (gather-only consumer)
__device__ float g_h1acc[(size_t)N_NODES * HID_];   // prop1 result; reused for prop2
__device__ __half g_hp3h[(size_t)N_NODES * HID_];   // gemm23 out, fp16 (gather-only consumer)
__device__ float g_as[N_NODES];
__device__ float g_ad[N_NODES];

// CSR by destination
__device__ int g_deg[N_NODES];
__device__ int g_start[N_NODES];
__device__ int g_cursor[N_NODES];
__device__ int g_csr_src[E_EDGES];
__device__ float g_csr_w[E_EDGES];

// prepped weights (all tf32, B[n][k] layout)
__device__ uint32_t g_b1t[256 * 512];               // W1^T  (N=256,K=512)
__device__ uint32_t g_b4t[512 * 256];               // W1    (N=512,K=256)
__device__ uint32_t g_b2t[64 * 256];                // W2^T  (N=64, K=256)
__device__ uint32_t g_b3t[256 * 64];                // W2    (N=256,K=64)

// ---------------- helpers -----------------------------------------------------
__device__ __forceinline__ float elu_f(float x) {
    return x > 0.f ? x : (expf(x) - 1.f);
}
__device__ __forceinline__ uint32_t f2tf32(float x) {
    uint32_t u;
    asm("cvt.rna.tf32.f32 %0, %1;" : "=r"(u) : "f"(x));
    return u;
}
__device__ __forceinline__ void mma_tf32(float* d, const uint32_t* a, const uint32_t* b) {
    asm volatile(
        "mma.sync.aligned.m16n8k8.row.col.f32.tf32.tf32.f32 "
        "{%0,%1,%2,%3}, {%4,%5,%6,%7}, {%8,%9}, {%0,%1,%2,%3};"
        : "+f"(d[0]), "+f"(d[1]), "+f"(d[2]), "+f"(d[3])
        : "r"(a[0]), "r"(a[1]), "r"(a[2]), "r"(a[3]), "r"(b[0]), "r"(b[1]));
}
// gather one fp16 row segment (8 halves) and accumulate into acc[8]
__device__ __forceinline__ void gather_h8(const __half* H, int si, int lane, float w,
                                          float* acc) {
    uint4 v = ((const uint4*)(H + (size_t)si * HID_))[lane];
    const __half2* hp = (const __half2*)&v;
    float2 p0 = __half22float2(hp[0]);
    float2 p1 = __half22float2(hp[1]);
    float2 p2 = __half22float2(hp[2]);
    float2 p3 = __half22float2(hp[3]);
    acc[0] = fmaf(p0.x, w, acc[0]); acc[1] = fmaf(p0.y, w, acc[1]);
    acc[2] = fmaf(p1.x, w, acc[2]); acc[3] = fmaf(p1.y, w, acc[3]);
    acc[4] = fmaf(p2.x, w, acc[4]); acc[5] = fmaf(p2.y, w, acc[5]);
    acc[6] = fmaf(p3.x, w, acc[6]); acc[7] = fmaf(p3.y, w, acc[7]);
}
__device__ __forceinline__ void write_row8(float* out, int d, int lane, const float* acc) {
    float4* orow = (float4*)(out + (size_t)d * HID_);
    orow[lane * 2]     = make_float4(acc[0], acc[1], acc[2], acc[3]);
    orow[lane * 2 + 1] = make_float4(acc[4], acc[5], acc[6], acc[7]);
}

// ---------------- CSR build ----------------------------------------------------
__global__ void zero_deg(int* deg) {
    int i = blockIdx.x * blockDim.x + threadIdx.x;
    if (i < N_NODES) deg[i] = 0;
}

__global__ void count_deg(const int* __restrict__ dst, int* __restrict__ deg) {
    int e = blockIdx.x * blockDim.x + threadIdx.x;
    if (e < E_EDGES) atomicAdd(&deg[dst[e]], 1);
}

__global__ void scan_deg(const int* __restrict__ deg, int* __restrict__ start,
                         int* __restrict__ cursor) {
    __shared__ int warp_sums[32];
    __shared__ int s_carry;
    if (threadIdx.x == 0) s_carry = 0;
    __syncthreads();
    const int tid = threadIdx.x;
    const int lane = tid & 31;
    const int wid = tid >> 5;
    for (int base = 0; base < N_NODES; base += 1024) {
        int i = base + tid;
        int v = (i < N_NODES) ? deg[i] : 0;
        int incl = v;
#pragma unroll
        for (int o = 1; o < 32; o <<= 1) {
            int t = __shfl_up_sync(0xffffffffu, incl, o);
            if (lane >= o) incl += t;
        }
        if (lane == 31) warp_sums[wid] = incl;
        __syncthreads();
        if (wid == 0) {
            int ws = warp_sums[lane];
            int wincl = ws;
#pragma unroll
            for (int o = 1; o < 32; o <<= 1) {
                int t = __shfl_up_sync(0xffffffffu, wincl, o);
                if (lane >= o) wincl += t;
            }
            warp_sums[lane] = wincl - ws;
        }
        __syncthreads();
        int excl = incl - v + warp_sums[wid] + s_carry;
        if (i < N_NODES) { start[i] = excl; cursor[i] = excl; }
        __syncthreads();
        if (tid == 1023) s_carry = excl + v;
        __syncthreads();
    }
}

__global__ void fill_csr(const int* __restrict__ src, const int* __restrict__ dst,
                         int* __restrict__ cursor, int* __restrict__ csr_src) {
    int e = blockIdx.x * blockDim.x + threadIdx.x;
    if (e >= E_EDGES) return;
    int pos = atomicAdd(&cursor[dst[e]], 1);
    csr_src[pos] = src[e];
}

// ---------------- fused softmax + propagate-1 (warp per dst, fp16 gather) -------
__global__ void __launch_bounds__(256)
softmax_prop(const int* __restrict__ start, const int* __restrict__ deg,
             const int* __restrict__ csr_src,
             const float* __restrict__ a_s, const float* __restrict__ a_d,
             float* __restrict__ csr_w,
             const __half* __restrict__ H, float* __restrict__ out) {
    int d = (blockIdx.x * blockDim.x + threadIdx.x) >> 5;
    int lane = threadIdx.x & 31;
    if (d >= N_NODES) return;
    int s0 = start[d], n = deg[d];

    float acc[8] = {0.f, 0.f, 0.f, 0.f, 0.f, 0.f, 0.f, 0.f};

    if (n > 0 && n <= 64) {
        float ad = a_d[d];
        int se0 = 0, se1 = 0;
        float l0 = -INFINITY, l1 = -INFINITY;
        if (lane < n) {
            se0 = csr_src[s0 + lane];
            float x = a_s[se0] + ad;
            l0 = x > 0.f ? x : 0.2f * x;
        }
        if (lane + 32 < n) {
            se1 = csr_src[s0 + lane + 32];
            float x = a_s[se1] + ad;
            l1 = x > 0.f ? x : 0.2f * x;
        }
        float mx = fmaxf(l0, l1);
#pragma unroll
        for (int o = 16; o; o >>= 1) mx = fmaxf(mx, __shfl_xor_sync(0xffffffffu, mx, o));
        float w0 = (lane < n) ? expf(l0 - mx) : 0.f;
        float w1 = (lane + 32 < n) ? expf(l1 - mx) : 0.f;
        float sum = w0 + w1;
#pragma unroll
        for (int o = 16; o; o >>= 1) sum += __shfl_xor_sync(0xffffffffu, sum, o);
        float inv = 1.f / (sum + 1e-16f);
        w0 *= inv; w1 *= inv;
        if (lane < n) csr_w[s0 + lane] = w0;
        if (lane + 32 < n) csr_w[s0 + lane + 32] = w1;

        for (int i = 0; i < n; i++) {
            int si; float wi;
            if (i < 32) {
                si = __shfl_sync(0xffffffffu, se0, i);
                wi = __shfl_sync(0xffffffffu, w0, i);
            } else {
                si = __shfl_sync(0xffffffffu, se1, i - 32);
                wi = __shfl_sync(0xffffffffu, w1, i - 32);
            }
            gather_h8(H, si, lane, wi, acc);
        }
    } else if (n > 64) {
        float ad = a_d[d];
        float mx = -INFINITY;
        for (int i = lane; i < n; i += 32) {
            float x = a_s[csr_src[s0 + i]] + ad;
            x = x > 0.f ? x : 0.2f * x;
            csr_w[s0 + i] = x;
            mx = fmaxf(mx, x);
        }
#pragma unroll
        for (int o = 16; o; o >>= 1) mx = fmaxf(mx, __shfl_xor_sync(0xffffffffu, mx, o));
        float sum = 0.f;
        for (int i = lane; i < n; i += 32) {
            float ex = expf(csr_w[s0 + i] - mx);
            csr_w[s0 + i] = ex;
            sum += ex;
        }
#pragma unroll
        for (int o = 16; o; o >>= 1) sum += __shfl_xor_sync(0xffffffffu, sum, o);
        float inv = 1.f / (sum + 1e-16f);
        for (int i = lane; i < n; i += 32) csr_w[s0 + i] *= inv;
        __threadfence_block();
        __syncwarp();
        for (int i = 0; i < n; i++) {
            int si = csr_src[s0 + i];
            float wi = csr_w[s0 + i];
            gather_h8(H, si, lane, wi, acc);
        }
    }
    write_row8(out, d, lane, acc);
}

// ---------------- propagate-2 (fp16 gather, register-resident sw) ---------------------
__global__ void __launch_bounds__(256)
propagate_csr(const int* __restrict__ start, const int* __restrict__ deg,
              const int* __restrict__ csr_src, const float* __restrict__ csr_w,
              const __half* __restrict__ H, float* __restrict__ out) {
    int d = (blockIdx.x * blockDim.x + threadIdx.x) >> 5;
    int lane = threadIdx.x & 31;
    if (d >= N_NODES) return;
    int s0 = start[d], n = deg[d];
    float acc[8] = {0.f, 0.f, 0.f, 0.f, 0.f, 0.f, 0.f, 0.f};

    if (n > 0 && n <= 64) {
        int se0 = 0, se1 = 0;
        float w0 = 0.f, w1 = 0.f;
        if (lane < n) { se0 = csr_src[s0 + lane]; w0 = csr_w[s0 + lane]; }
        if (lane + 32 < n) { se1 = csr_src[s0 + lane + 32]; w1 = csr_w[s0 + lane + 32]; }
        for (int i = 0; i < n; i++) {
            int si; float wi;
            if (i < 32) { si = __shfl_sync(0xffffffffu, se0, i); wi = __shfl_sync(0xffffffffu, w0, i); }
            else        { si = __shfl_sync(0xffffffffu, se1, i - 32); wi = __shfl_sync(0xffffffffu, w1, i - 32); }
            gather_h8(H, si, lane, wi, acc);
        }
    } else if (n > 64) {
        for (int i = 0; i < n; i++) {
            int si = csr_src[s0 + i];
            float wi = csr_w[s0 + i];
            gather_h8(H, si, lane, wi, acc);
        }
    }
    write_row8(out, d, lane, acc);
}

// ---------------- weight prep (all tf32, + zero a_s/a_d) -----------------------------
__global__ void prep_weights(const float* __restrict__ W1, const float* __restrict__ W2,
                             uint32_t* b1t, uint32_t* b4t,
                             uint32_t* b2t, uint32_t* b3t,
                             float* a_s, float* a_d) {
    int i = blockIdx.x * blockDim.x + threadIdx.x;
    if (i < N_NODES) { a_s[i] = 0.f; a_d[i] = 0.f; }
    if (i < 512 * 256) {
        int k = i >> 8, n = i & 255;
        uint32_t t = f2tf32(W1[i]);
        b4t[i] = t;
        b1t[n * 512 + k] = t;
    }
    if (i < 256 * 64) {
        int k = i >> 6, n = i & 63;
        uint32_t t = f2tf32(W2[i]);
        b3t[i] = t;
        b2t[n * 256 + k] = t;
    }
}

// ---------------- unified tf32 GEMM (straight layout, conflict-free) -----------------
// HOUT: write C as fp16 (half2 pairs); else fp32.
template <bool ELUA, bool ATT, bool HOUT>
__global__ void __launch_bounds__(512)
tf32_gemm(const float* __restrict__ A, const uint32_t* __restrict__ Bt,
          void* __restrict__ Cv, int M, int N, int K,
          const float* __restrict__ attS, const float* __restrict__ attD,
          float* __restrict__ a_s, float* __restrict__ a_d) {
    constexpr int SPF = 36;
    constexpr int TSZ = 128 * SPF;

    extern __shared__ uint32_t smu[];

    const int tid = threadIdx.x;
    const int wid = tid >> 5;
    const int lane = tid & 31;
    const int wm = wid >> 2;
    const int wn = wid & 3;
    const int rowBase = blockIdx.y * 128;
    const int colBase = blockIdx.x * 128;
    const int nk = K >> 5;

    float acc[2][4][4];
#pragma unroll
    for (int i = 0; i < 2; i++)
#pragma unroll
        for (int j = 0; j < 4; j++)
#pragma unroll
            for (int c = 0; c < 4; c++) acc[i][j][c] = 0.f;

    float4 aR[2];
    uint4 bR[2];

    auto load_regs = [&](int t) {
#pragma unroll
        for (int i = 0; i < 2; i++) {
            int u = tid + i * 512;
            int r = u >> 3, q = u & 7;
            int grow = rowBase + r;
            aR[i] = make_float4(0.f, 0.f, 0.f, 0.f);
            if (grow < M) aR[i] = *(const float4*)(A + (size_t)grow * K + t * 32 + q * 4);
            bR[i] = *(const uint4*)(Bt + (size_t)(colBase + r) * K + t * 32 + q * 4);
        }
    };

    auto store_smem = [&](int s) {
        uint32_t* sA = smu + s * (2 * TSZ);
        uint32_t* sB = sA + TSZ;
#pragma unroll
        for (int i = 0; i < 2; i++) {
            int u = tid + i * 512;
            int r = u >> 3, q = u & 7;
            float4 va = aR[i];
            if (ELUA) {
                va.x = elu_f(va.x); va.y = elu_f(va.y);
                va.z = elu_f(va.z); va.w = elu_f(va.w);
            }
            uint4 ta = make_uint4(f2tf32(va.x), f2tf32(va.y), f2tf32(va.z), f2tf32(va.w));
            *(uint4*)&sA[r * SPF + q * 4] = ta;
            *(uint4*)&sB[r * SPF + q * 4] = bR[i];
        }
    };

    const int g = lane >> 2;
    const int t4 = lane & 3;

    auto compute = [&](int s) {
        const uint32_t* sA = smu + s * (2 * TSZ);
        const uint32_t* sB = sA + TSZ;
#pragma unroll
        for (int ks = 0; ks < 4; ks++) {
            int cb = ks * 8 + t4;
            uint32_t a[2][4];
#pragma unroll
            for (int mt = 0; mt < 2; mt++) {
                int rb = wm * 32 + mt * 16;
                a[mt][0] = sA[(rb + g) * SPF + cb];
                a[mt][1] = sA[(rb + g + 8) * SPF + cb];
                a[mt][2] = sA[(rb + g) * SPF + cb + 4];
                a[mt][3] = sA[(rb + g + 8) * SPF + cb + 4];
            }
            uint32_t b[4][2];
#pragma unroll
            for (int nt = 0; nt < 4; nt++) {
                int nb = wn * 32 + nt * 8 + g;
                b[nt][0] = sB[nb * SPF + cb];
                b[nt][1] = sB[nb * SPF + cb + 4];
            }
#pragma unroll
            for (int mt = 0; mt < 2; mt++)
#pragma unroll
                for (int nt = 0; nt < 4; nt++)
                    mma_tf32(acc[mt][nt], a[mt], b[nt]);
        }
    };

    load_regs(0);
    store_smem(0);
    __syncthreads();
    for (int t = 0; t < nk; t++) {
        if (t + 1 < nk) load_regs(t + 1);
        compute(t & 1);
        if (t + 1 < nk) store_smem((t + 1) & 1);
        __syncthreads();
    }

    const int t2 = (lane & 3) * 2;
#pragma unroll
    for (int mt = 0; mt < 2; mt++) {
        int row0 = rowBase + wm * 32 + mt * 16 + g;
#pragma unroll
        for (int nt = 0; nt < 4; nt++) {
            int col = colBase + wn * 32 + nt * 8 + t2;
            if (HOUT) {
                __half* C = (__half*)Cv;
                if (row0 < M)
                    *(__half2*)&C[(size_t)row0 * N + col] =
                        __floats2half2_rn(acc[mt][nt][0], acc[mt][nt][1]);
                if (row0 + 8 < M)
                    *(__half2*)&C[(size_t)(row0 + 8) * N + col] =
                        __floats2half2_rn(acc[mt][nt][2], acc[mt][nt][3]);
            } else {
                float* C = (float*)Cv;
                if (row0 < M)
                    *(float2*)&C[(size_t)row0 * N + col] =
                        make_float2(acc[mt][nt][0], acc[mt][nt][1]);
                if (row0 + 8 < M)
                    *(float2*)&C[(size_t)(row0 + 8) * N + col] =
                        make_float2(acc[mt][nt][2], acc[mt][nt][3]);
            }
        }
    }

    if (ATT) {
#pragma unroll
        for (int mt = 0; mt < 2; mt++) {
            int row0 = rowBase + wm * 32 + mt * 16 + g;
            float sp0 = 0.f, sp1 = 0.f, dp0 = 0.f, dp1 = 0.f;
#pragma unroll
            for (int nt = 0; nt < 4; nt++) {
                int col = colBase + wn * 32 + nt * 8 + t2;
                float s0 = attS[col], s1 = attS[col + 1];
                float d0 = attD[col], d1 = attD[col + 1];
                sp0 += acc[mt][nt][0] * s0 + acc[mt][nt][1] * s1;
                sp1 += acc[mt][nt][2] * s0 + acc[mt][nt][3] * s1;
                dp0 += acc[mt][nt][0] * d0 + acc[mt][nt][1] * d1;
                dp1 += acc[mt][nt][2] * d0 + acc[mt][nt][3] * d1;
            }
#pragma unroll
            for (int o = 1; o <= 2; o <<= 1) {
                sp0 += __shfl_xor_sync(0xffffffffu, sp0, o);
                sp1 += __shfl_xor_sync(0xffffffffu, sp1, o);
                dp0 += __shfl_xor_sync(0xffffffffu, dp0, o);
                dp1 += __shfl_xor_sync(0xffffffffu, dp1, o);
            }
            if ((lane & 3) == 0) {
                if (row0 < M) {
                    atomicAdd(&a_s[row0], sp0);
                    atomicAdd(&a_d[row0], dp0);
                }
                if (row0 + 8 < M) {
                    atomicAdd(&a_s[row0 + 8], sp1);
                    atomicAdd(&a_d[row0 + 8], dp1);
                }
            }
        }
    }
}

// ---------------- fused GEMM2 + GEMM3 (tf32; hp3 out as fp16) -------------------------
__global__ void __launch_bounds__(512)
gemm23_tf32(const float* __restrict__ A,
            const uint32_t* __restrict__ B2t, const uint32_t* __restrict__ B3t,
            float* __restrict__ H2, __half* __restrict__ HP3, int M) {
    constexpr int SPF = 36;
    constexpr int ATSZ = 128 * SPF;
    constexpr int BTSZ = 64 * SPF;
    constexpr int SPF2 = 68;
    constexpr int HWORDS = 128 * SPF2;

    extern __shared__ uint32_t smu[];

    const int tid = threadIdx.x;
    const int wid = tid >> 5;
    const int lane = tid & 31;
    const int rowBase = blockIdx.y * 128;

    const int g = lane >> 2;
    const int t4 = lane & 3;
    const int t2 = (lane & 3) * 2;

    // stage 1
    {
        const int wm = wid >> 2;
        const int wn = wid & 3;
        float acc1[2][2][4];
#pragma unroll
        for (int i = 0; i < 2; i++)
#pragma unroll
            for (int j = 0; j < 2; j++)
#pragma unroll
                for (int c = 0; c < 4; c++) acc1[i][j][c] = 0.f;

        float4 aR[2];
        uint4 bR;
        const int br = tid >> 3, bq = tid & 7;

        auto load1 = [&](int t) {
#pragma unroll
            for (int i = 0; i < 2; i++) {
                int u = tid + i * 512;
                int r = u >> 3, q = u & 7;
                int grow = rowBase + r;
                aR[i] = make_float4(0.f, 0.f, 0.f, 0.f);
                if (grow < M) aR[i] = *(const float4*)(A + (size_t)grow * 256 + t * 32 + q * 4);
            }
            bR = *(const uint4*)(B2t + (size_t)br * 256 + t * 32 + bq * 4);
        };
        auto store1 = [&](int s) {
            uint32_t* sA = smu + s * ATSZ;
            uint32_t* sB = smu + 2 * ATSZ + s * BTSZ;
#pragma unroll
            for (int i = 0; i < 2; i++) {
                int u = tid + i * 512;
                int r = u >> 3, q = u & 7;
                float4 v = aR[i];
                v.x = elu_f(v.x); v.y = elu_f(v.y);
                v.z = elu_f(v.z); v.w = elu_f(v.w);
                uint4 ta = make_uint4(f2tf32(v.x), f2tf32(v.y), f2tf32(v.z), f2tf32(v.w));
                *(uint4*)&sA[r * SPF + q * 4] = ta;
            }
            *(uint4*)&sB[br * SPF + bq * 4] = bR;
        };
        auto compute1 = [&](int s) {
            const uint32_t* sA = smu + s * ATSZ;
            const uint32_t* sB = smu + 2 * ATSZ + s * BTSZ;
#pragma unroll
            for (int ks = 0; ks < 4; ks++) {
                int cb = ks * 8 + t4;
                uint32_t a[2][4];
#pragma unroll
                for (int mt = 0; mt < 2; mt++) {
                    int rb = wm * 32 + mt * 16;
                    a[mt][0] = sA[(rb + g) * SPF + cb];
                    a[mt][1] = sA[(rb + g + 8) * SPF + cb];
                    a[mt][2] = sA[(rb + g) * SPF + cb + 4];
                    a[mt][3] = sA[(rb + g + 8) * SPF + cb + 4];
                }
                uint32_t b[2][2];
#pragma unroll
                for (int nt = 0; nt < 2; nt++) {
                    int nb = wn * 16 + nt * 8 + g;
                    b[nt][0] = sB[nb * SPF + cb];
                    b[nt][1] = sB[nb * SPF + cb + 4];
                }
#pragma unroll
                for (int mt = 0; mt < 2; mt++)
#pragma unroll
                    for (int nt = 0; nt < 2; nt++)
                        mma_tf32(acc1[mt][nt], a[mt], b[nt]);
            }
        };

        load1(0);
        store1(0);
        __syncthreads();
        for (int t = 0; t < 8; t++) {
            if (t + 1 < 8) load1(t + 1);
            compute1(t & 1);
            if (t + 1 < 8) store1((t + 1) & 1);
            __syncthreads();
        }

        uint32_t* sH = smu;
#pragma unroll
        for (int mt = 0; mt < 2; mt++) {
            int rl0 = wm * 32 + mt * 16 + g;
#pragma unroll
            for (int nt = 0; nt < 2; nt++) {
                int col = wn * 16 + nt * 8 + t2;
                float v0 = acc1[mt][nt][0], v1 = acc1[mt][nt][1];
                float v2 = acc1[mt][nt][2], v3 = acc1[mt][nt][3];
                int grow0 = rowBase + rl0;
                if (grow0 < M) *(float2*)&H2[(size_t)grow0 * 64 + col] = make_float2(v0, v1);
                if (grow0 + 8 < M) *(float2*)&H2[(size_t)(grow0 + 8) * 64 + col] = make_float2(v2, v3);
                sH[rl0 * SPF2 + col] = f2tf32(v0);
                sH[rl0 * SPF2 + col + 1] = f2tf32(v1);
                sH[(rl0 + 8) * SPF2 + col] = f2tf32(v2);
                sH[(rl0 + 8) * SPF2 + col + 1] = f2tf32(v3);
            }
        }
    }
    __syncthreads();

    // stage 2
    {
        uint32_t* sB3 = smu + HWORDS;
#pragma unroll
        for (int i = 0; i < 8; i++) {
            int u = tid + i * 512;
            int r = u >> 4, q = u & 15;
            *(uint4*)&sB3[r * SPF2 + q * 4] = *(const uint4*)(B3t + r * 64 + q * 4);
        }
        __syncthreads();

        const int wm = wid >> 3;
        const int wn = wid & 7;
        float acc2[4][4][4];
#pragma unroll
        for (int i = 0; i < 4; i++)
#pragma unroll
            for (int j = 0; j < 4; j++)
#pragma unroll
                for (int c = 0; c < 4; c++) acc2[i][j][c] = 0.f;

        const uint32_t* sH = smu;
#pragma unroll
        for (int ks = 0; ks < 8; ks++) {
            int cb = ks * 8 + t4;
            uint32_t a[4][4];
#pragma unroll
            for (int mt = 0; mt < 4; mt++) {
                int rb = wm * 64 + mt * 16;
                a[mt][0] = sH[(rb + g) * SPF2 + cb];
                a[mt][1] = sH[(rb + g + 8) * SPF2 + cb];
                a[mt][2] = sH[(rb + g) * SPF2 + cb + 4];
                a[mt][3] = sH[(rb + g + 8) * SPF2 + cb + 4];
            }
            uint32_t b[4][2];
#pragma unroll
            for (int nt = 0; nt < 4; nt++) {
                int nb = wn * 32 + nt * 8 + g;
                b[nt][0] = sB3[nb * SPF2 + cb];
                b[nt][1] = sB3[nb * SPF2 + cb + 4];
            }
#pragma unroll
            for (int mt = 0; mt < 4; mt++)
#pragma unroll
                for (int nt = 0; nt < 4; nt++)
                    mma_tf32(acc2[mt][nt], a[mt], b[nt]);
        }

#pragma unroll
        for (int mt = 0; mt < 4; mt++) {
            int row0 = rowBase + wm * 64 + mt * 16 + g;
#pragma unroll
            for (int nt = 0; nt < 4; nt++) {
                int col = wn * 32 + nt * 8 + t2;
                if (row0 < M)
                    *(__half2*)&HP3[(size_t)row0 * 256 + col] =
                        __floats2half2_rn(acc2[mt][nt][0], acc2[mt][nt][1]);
                if (row0 + 8 < M)
                    *(__half2*)&HP3[(size_t)(row0 + 8) * 256 + col] =
                        __floats2half2_rn(acc2[mt][nt][2], acc2[mt][nt][3]);
            }
        }
    }
}

// ---------------- launch --------------------------------------------------------------
extern "C" void kernel_launch(void* const* d_in, const int* in_sizes, int n_in,
                              void* d_out, int out_size) {
    const float* features = (const float*)d_in[0];
    const float* W1       = (const float*)d_in[1];
    const float* W2       = (const float*)d_in[2];
    const float* att_src  = (const float*)d_in[3];
    const float* att_dst  = (const float*)d_in[4];
    const int*   edge     = (const int*)d_in[5];
    const int* src = edge;
    const int* dst = edge + E_EDGES;

    float* out = (float*)d_out;
    float* h2 = out;
    float* h4 = out + (size_t)N_NODES * OUT_DIM_;

    __half *hp1h, *hp3h;
    float *h1acc, *a_s, *a_d;
    cudaGetSymbolAddress((void**)&hp1h,  g_hp1h);
    cudaGetSymbolAddress((void**)&h1acc, g_h1acc);
    cudaGetSymbolAddress((void**)&hp3h,  g_hp3h);
    cudaGetSymbolAddress((void**)&a_s,   g_as);
    cudaGetSymbolAddress((void**)&a_d,   g_ad);

    int *deg, *start, *cursor, *csr_src;
    float* csr_w;
    cudaGetSymbolAddress((void**)&deg,     g_deg);
    cudaGetSymbolAddress((void**)&start,   g_start);
    cudaGetSymbolAddress((void**)&cursor,  g_cursor);
    cudaGetSymbolAddress((void**)&csr_src, g_csr_src);
    cudaGetSymbolAddress((void**)&csr_w,   g_csr_w);

    uint32_t *b1t, *b4t, *b2t, *b3t;
    cudaGetSymbolAddress((void**)&b1t, g_b1t);
    cudaGetSymbolAddress((void**)&b4t, g_b4t);
    cudaGetSymbolAddress((void**)&b2t, g_b2t);
    cudaGetSymbolAddress((void**)&b3t, g_b3t);

    const int smemTf = 2 * 2 * 128 * 36 * 4;                 // 73728
    const int smem23 = (128 * 68 + 256 * 68) * 4;            // 104448
    cudaFuncSetAttribute(tf32_gemm<false, true, true>,
                         cudaFuncAttributeMaxDynamicSharedMemorySize, smemTf);
    cudaFuncSetAttribute(tf32_gemm<true, false, false>,
                         cudaFuncAttributeMaxDynamicSharedMemorySize, smemTf);
    cudaFuncSetAttribute(gemm23_tf32,
                         cudaFuncAttributeMaxDynamicSharedMemorySize, smem23);

    const int mtiles = (N_NODES + 127) / 128;   // 391
    const int nodeWarpGrid = (N_NODES * 32 + 255) / 256;

    // fork: CSR build on s2, overlapped with prep + GEMM1 on main
    cudaStream_t s2;
    cudaStreamCreateWithFlags(&s2, cudaStreamNonBlocking);
    cudaEvent_t e1, e_csr;
    cudaEventCreateWithFlags(&e1,    cudaEventDisableTiming);
    cudaEventCreateWithFlags(&e_csr, cudaEventDisableTiming);

    cudaEventRecord(e1, 0);
    cudaStreamWaitEvent(s2, e1, 0);
    zero_deg<<<(N_NODES + 255) / 256, 256, 0, s2>>>(deg);
    count_deg<<<(E_EDGES + 255) / 256, 256, 0, s2>>>(dst, deg);
    scan_deg<<<1, 1024, 0, s2>>>(deg, start, cursor);
    fill_csr<<<(E_EDGES + 255) / 256, 256, 0, s2>>>(src, dst, cursor, csr_src);
    cudaEventRecord(e_csr, s2);

    // main chain
    prep_weights<<<(512 * 256 + 255) / 256, 256>>>(W1, W2, b1t, b4t, b2t, b3t, a_s, a_d);
    // GEMM1: hp1(fp16) = features @ W1  (tf32, fused attention dots from fp32 acc)
    tf32_gemm<false, true, true><<<dim3(2, mtiles), 512, smemTf>>>(
        features, b1t, hp1h, N_NODES, HID_, IN_DIM_, att_src, att_dst, a_s, a_d);

    cudaStreamWaitEvent(0, e_csr, 0);

    softmax_prop<<<nodeWarpGrid, 256>>>(start, deg, csr_src, a_s, a_d, csr_w, hp1h, h1acc);
    gemm23_tf32<<<dim3(1, mtiles), 512, smem23>>>(h1acc, b2t, b3t, h2, hp3h, N_NODES);
    propagate_csr<<<nodeWarpGrid, 256>>>(start, deg, csr_src, csr_w, hp3h, h1acc);
    // GEMM4: h4 = elu(h1acc) @ W1^T  (tf32, fp32 out)
    tf32_gemm<true, false, false><<<dim3(4, mtiles), 512, smemTf>>>(
        h1acc, b4t, h4, N_NODES, IN_DIM_, HID_, nullptr, nullptr, nullptr, nullptr);

    (void)in_sizes; (void)n_in; (void)out_size;
}